// round 1
// baseline (speedup 1.0000x reference)
#include <cuda_runtime.h>
#include <math.h>

// Problem constants
#define BB   4
#define NTOK 4096
#define DM   1024
#define DH   256
#define SM_  256
#define HIDN 32
#define MTOT (BB*NTOK)   // 16384

// ---------------- scratch (static device arrays; no runtime allocation) ----------
__device__ float g_ctx[BB*DM];
__device__ float g_gamma[BB];
__device__ float g_p[MTOT];
__device__ float g_ppc[(size_t)MTOT*512];     // [pr | pi] concat over dH
__device__ float g_Bcat[512*512];             // [[Mr^T, Mi^T],[Mi^T, -Mr^T]]
__device__ float g_reim[(size_t)MTOT*512];    // [re | im]
__device__ float g_attn[(size_t)MTOT*256];
__device__ float g_av[(size_t)MTOT*1024];
__device__ float g_ao[(size_t)MTOT*1024];
__device__ float g_h1[(size_t)MTOT*1024];
__device__ float g_ffi[(size_t)MTOT*4096];
__device__ float g_ff2[(size_t)MTOT*1024];

__device__ __forceinline__ float warp_sum(float v) {
#pragma unroll
    for (int o = 16; o > 0; o >>= 1) v += __shfl_xor_sync(0xffffffffu, v, o);
    return v;
}

__device__ __forceinline__ float gelu_exact(float x) {
    return 0.5f * x * (1.0f + erff(x * 0.70710678118654752440f));
}

// ---------------- ctx = mean over N ----------------
__global__ void ctx_kernel(const float* __restrict__ h) {
    int d = blockIdx.x * blockDim.x + threadIdx.x;   // 0..1023
    int b = blockIdx.y;
    const float* hp = h + ((size_t)b * NTOK) * DM + d;
    float s = 0.f;
    for (int n = 0; n < NTOK; n++) s += hp[(size_t)n * DM];
    g_ctx[b * DM + d] = s * (1.0f / NTOK);
}

// ---------------- gamma = gate(ctx) : 1 warp per batch ----------------
__global__ void gamma_kernel(const float* __restrict__ gw1, const float* __restrict__ gb1,
                             const float* __restrict__ gg,  const float* __restrict__ gbeta,
                             const float* __restrict__ gw2, const float* __restrict__ gb2) {
    int b = blockIdx.x;
    int j = threadIdx.x;  // 0..31
    const float* c = g_ctx + b * DM;
    float t = gb1[j];
    for (int k = 0; k < DM; k++) t += c[k] * gw1[k * HIDN + j];
    float mu  = warp_sum(t) * (1.f / 32.f);
    float dv  = t - mu;
    float var = warp_sum(dv * dv) * (1.f / 32.f);
    float tn  = dv * rsqrtf(var + 1e-5f) * gg[j] + gbeta[j];
    float s   = tn / (1.f + expf(-tn));              // silu
    float z   = warp_sum(s * gw2[j]);
    if (j == 0) g_gamma[b] = 1.f / (1.f + expf(-(z + gb2[0])));
}

// ---------------- normalize memory + build Bcat ----------------
__global__ void mem_kernel(const float* __restrict__ m_real, const float* __restrict__ m_imag) {
    int s = blockIdx.x;   // 0..255
    int k = threadIdx.x;  // 0..255
    float mr = m_real[s * DH + k];
    float mi = m_imag[s * DH + k];
    __shared__ float red[256];
    red[k] = mr * mr + mi * mi;
    __syncthreads();
    for (int o = 128; o > 0; o >>= 1) { if (k < o) red[k] += red[k + o]; __syncthreads(); }
    __shared__ float sc;
    if (k == 0) sc = 1.f / fmaxf(sqrtf(red[0]), 1e-12f);
    __syncthreads();
    float a = mr * sc, b = mi * sc;
    g_Bcat[k * 512 + s]               = a;    // Bre top   : Mr_n[s][k]
    g_Bcat[(256 + k) * 512 + s]       = b;    // Bre bottom: Mi_n[s][k]
    g_Bcat[k * 512 + 256 + s]         = b;    // Bim top   : Mi_n[s][k]
    g_Bcat[(256 + k) * 512 + 256 + s] = -a;   // Bim bottom: -Mr_n[s][k]
}

// ---------------- per-token: normalize psi, uncertainty gate, p ----------------
__global__ void rownorm_gate_kernel(const float* __restrict__ h,
    const float* __restrict__ uw1, const float* __restrict__ ub1,
    const float* __restrict__ ug,  const float* __restrict__ ubeta,
    const float* __restrict__ uw2, const float* __restrict__ ub2) {
    int m = blockIdx.x;
    int tid = threadIdx.x;  // 0..255
    float* row = g_ppc + (size_t)m * 512;
    float v0 = row[tid], v1 = row[256 + tid];
    __shared__ float red[256];
    red[tid] = v0 * v0 + v1 * v1;
    __syncthreads();
    for (int o = 128; o > 0; o >>= 1) { if (tid < o) red[tid] += red[tid + o]; __syncthreads(); }
    __shared__ float sc;
    if (tid == 0) sc = 1.f / fmaxf(sqrtf(red[0]), 1e-12f);
    __syncthreads();
    row[tid] = v0 * sc;
    row[256 + tid] = v1 * sc;

    // uncertainty gate: 32 outputs x 8 partial threads
    int j = tid & 31, part = tid >> 5;
    const float* hr = h + (size_t)m * DM;
    float partial = 0.f;
    int k0 = part * 128;
    for (int k = k0; k < k0 + 128; k++) partial += hr[k] * uw1[k * HIDN + j];
    __shared__ float gred[8][32];
    gred[part][j] = partial;
    __syncthreads();
    if (tid < 32) {
        float t = ub1[tid];
#pragma unroll
        for (int q = 0; q < 8; q++) t += gred[q][tid];
        float mu  = warp_sum(t) * (1.f / 32.f);
        float dv  = t - mu;
        float var = warp_sum(dv * dv) * (1.f / 32.f);
        float tn  = dv * rsqrtf(var + 1e-5f) * ug[tid] + ubeta[tid];
        float s   = tn / (1.f + expf(-tn));
        float z   = warp_sum(s * uw2[tid]);
        if (tid == 0) {
            float pin = 0.95f / (1.f + expf(-(z + ub2[0])));
            g_p[m] = pin * (1.f - g_gamma[m >> 12]);   // m/4096 = batch
        }
    }
}

// ---------------- attention row: overlap -> raw -> normalize ----------------
__global__ void attn_kernel() {
    int m = blockIdx.x;
    int s = threadIdx.x;  // 0..255
    float re = g_reim[(size_t)m * 512 + s];
    float im = g_reim[(size_t)m * 512 + 256 + s];
    float pm = g_p[m];
    float raw = (1.f - pm) * (re * re + im * im) + pm * (1.f / 256.f);
    __shared__ float red[256];
    red[s] = raw;
    __syncthreads();
    for (int o = 128; o > 0; o >>= 1) { if (s < o) red[s] += red[s + o]; __syncthreads(); }
    g_attn[(size_t)m * 256 + s] = raw / (red[0] + 1e-8f);
}

// ---------------- LayerNorm(x + y) ----------------
__global__ void ln_kernel(const float* __restrict__ x, const float* __restrict__ y,
                          const float* __restrict__ g, const float* __restrict__ bta,
                          float* __restrict__ out) {
    int m = blockIdx.x;
    int tid = threadIdx.x;  // 0..255, 4 elems each
    size_t base = (size_t)m * DM;
    float v[4];
    float s1 = 0.f, s2 = 0.f;
#pragma unroll
    for (int i = 0; i < 4; i++) {
        int d = tid + 256 * i;
        v[i] = x[base + d] + y[base + d];
        s1 += v[i];
        s2 += v[i] * v[i];
    }
    __shared__ float r1[256], r2[256];
    r1[tid] = s1; r2[tid] = s2;
    __syncthreads();
    for (int o = 128; o > 0; o >>= 1) {
        if (tid < o) { r1[tid] += r1[tid + o]; r2[tid] += r2[tid + o]; }
        __syncthreads();
    }
    float mu  = r1[0] * (1.f / 1024.f);
    float var = r2[0] * (1.f / 1024.f) - mu * mu;
    float inv = rsqrtf(var + 1e-5f);
#pragma unroll
    for (int i = 0; i < 4; i++) {
        int d = tid + 256 * i;
        out[base + d] = (v[i] - mu) * inv * g[d] + bta[d];
    }
}

// ---------------- generic fp32 SGEMM: C = A(MxK) @ B(KxN) [+bias][+gelu] ----------
// BM=BN=128, BK=8, 256 threads, 8x8 per-thread tile. All dims divisible.
#define GBM 128
#define GBN 128
#define GBK 8
#define GTM 8
#define GTN 8

template <int EPI>  // 0: none, 1: +bias, 2: +bias + exact gelu
__global__ __launch_bounds__(256, 2) void sgemm_kernel(
    const float* __restrict__ A, const float* __restrict__ B,
    const float* __restrict__ bias, float* __restrict__ C,
    int M, int N, int K, int lda, int ldb, int ldc) {
    __shared__ float As[GBK][GBM];
    __shared__ float Bs[GBK][GBN];
    int tid = threadIdx.x;
    int row0 = blockIdx.y * GBM;
    int col0 = blockIdx.x * GBN;

    int a_r = tid >> 1;            // 0..127
    int a_c = (tid & 1) << 2;      // 0 or 4
    int b_r = tid >> 5;            // 0..7
    int b_c = (tid & 31) << 2;     // 0..124

    const float* Aptr = A + (size_t)(row0 + a_r) * lda + a_c;
    const float* Bptr = B + (size_t)b_r * ldb + col0 + b_c;

    int ty = tid >> 4, tx = tid & 15;

    float acc[GTM][GTN];
#pragma unroll
    for (int i = 0; i < GTM; i++)
#pragma unroll
        for (int j = 0; j < GTN; j++) acc[i][j] = 0.f;

    float ra[GTM], rb[GTN];

    for (int k0 = 0; k0 < K; k0 += GBK) {
        float4 av = *(const float4*)(Aptr);
        Aptr += GBK;
        As[a_c + 0][a_r] = av.x;
        As[a_c + 1][a_r] = av.y;
        As[a_c + 2][a_r] = av.z;
        As[a_c + 3][a_r] = av.w;
        float4 bv = *(const float4*)(Bptr);
        Bptr += (size_t)GBK * ldb;
        *(float4*)&Bs[b_r][b_c] = bv;
        __syncthreads();
#pragma unroll
        for (int k = 0; k < GBK; k++) {
            *(float4*)&ra[0] = *(const float4*)&As[k][ty * GTM];
            *(float4*)&ra[4] = *(const float4*)&As[k][ty * GTM + 4];
            *(float4*)&rb[0] = *(const float4*)&Bs[k][tx * GTN];
            *(float4*)&rb[4] = *(const float4*)&Bs[k][tx * GTN + 4];
#pragma unroll
            for (int i = 0; i < GTM; i++)
#pragma unroll
                for (int j = 0; j < GTN; j++) acc[i][j] += ra[i] * rb[j];
        }
        __syncthreads();
    }

    float bv[GTN];
#pragma unroll
    for (int j = 0; j < GTN; j++) bv[j] = 0.f;
    if (EPI > 0) {
#pragma unroll
        for (int j = 0; j < GTN; j++) bv[j] = bias[col0 + tx * GTN + j];
    }
#pragma unroll
    for (int i = 0; i < GTM; i++) {
        int r = row0 + ty * GTM + i;
        float outv[GTN];
#pragma unroll
        for (int j = 0; j < GTN; j++) {
            float v = acc[i][j] + bv[j];
            if (EPI == 2) v = gelu_exact(v);
            outv[j] = v;
        }
        float* cp = C + (size_t)r * ldc + col0 + tx * GTN;
        *(float4*)cp       = *(float4*)&outv[0];
        *(float4*)(cp + 4) = *(float4*)&outv[4];
    }
}

// ---------------- launch ----------------
extern "C" void kernel_launch(void* const* d_in, const int* in_sizes, int n_in,
                              void* d_out, int out_size) {
    const float* h      = (const float*)d_in[0];
    const float* Wr     = (const float*)d_in[1];
    const float* br     = (const float*)d_in[2];
    const float* Wi     = (const float*)d_in[3];
    const float* bi     = (const float*)d_in[4];
    const float* uw1    = (const float*)d_in[5];
    const float* ub1    = (const float*)d_in[6];
    const float* ug     = (const float*)d_in[7];
    const float* ubeta  = (const float*)d_in[8];
    const float* uw2    = (const float*)d_in[9];
    const float* ub2    = (const float*)d_in[10];
    const float* gw1    = (const float*)d_in[11];
    const float* gb1    = (const float*)d_in[12];
    const float* gg     = (const float*)d_in[13];
    const float* gbeta  = (const float*)d_in[14];
    const float* gw2    = (const float*)d_in[15];
    const float* gb2    = (const float*)d_in[16];
    const float* m_real = (const float*)d_in[17];
    const float* m_imag = (const float*)d_in[18];
    const float* values = (const float*)d_in[19];
    const float* ow     = (const float*)d_in[20];
    const float* ob     = (const float*)d_in[21];
    const float* n1g    = (const float*)d_in[22];
    const float* n1b    = (const float*)d_in[23];
    const float* n2g    = (const float*)d_in[24];
    const float* n2b    = (const float*)d_in[25];
    const float* fw1    = (const float*)d_in[26];
    const float* fb1    = (const float*)d_in[27];
    const float* fw2    = (const float*)d_in[28];
    const float* fb2    = (const float*)d_in[29];
    float* out = (float*)d_out;

    float *ppc, *Bcat, *reim, *attn, *av, *ao, *h1, *ffi, *ff2;
    cudaGetSymbolAddress((void**)&ppc,  g_ppc);
    cudaGetSymbolAddress((void**)&Bcat, g_Bcat);
    cudaGetSymbolAddress((void**)&reim, g_reim);
    cudaGetSymbolAddress((void**)&attn, g_attn);
    cudaGetSymbolAddress((void**)&av,   g_av);
    cudaGetSymbolAddress((void**)&ao,   g_ao);
    cudaGetSymbolAddress((void**)&h1,   g_h1);
    cudaGetSymbolAddress((void**)&ffi,  g_ffi);
    cudaGetSymbolAddress((void**)&ff2,  g_ff2);

    // context + decoherence gamma + memory normalization
    ctx_kernel<<<dim3(DM / 256, BB), 256>>>(h);
    gamma_kernel<<<BB, 32>>>(gw1, gb1, gg, gbeta, gw2, gb2);
    mem_kernel<<<SM_, 256>>>(m_real, m_imag);

    // encoder: pr | pi  -> ppc (M,512)
    sgemm_kernel<1><<<dim3(2, MTOT / GBM), 256>>>(h, Wr, br, ppc,       MTOT, 256,  1024, 1024, 256,  512);
    sgemm_kernel<1><<<dim3(2, MTOT / GBM), 256>>>(h, Wi, bi, ppc + 256, MTOT, 256,  1024, 1024, 256,  512);

    // psi normalize + uncertainty gate + p
    rownorm_gate_kernel<<<MTOT, 256>>>(h, uw1, ub1, ug, ubeta, uw2, ub2);

    // complex overlap as one GEMM: reim = ppc @ Bcat  (M,512)
    sgemm_kernel<0><<<dim3(4, MTOT / GBM), 256>>>(ppc, Bcat, nullptr, reim, MTOT, 512,  512,  512,  512,  512);

    // attn weights
    attn_kernel<<<MTOT, 256>>>();

    // attn @ values -> av ; av @ ow + ob -> ao
    sgemm_kernel<0><<<dim3(8, MTOT / GBM), 256>>>(attn, values, nullptr, av, MTOT, 1024, 256,  256,  1024, 1024);
    sgemm_kernel<1><<<dim3(8, MTOT / GBM), 256>>>(av,   ow,     ob,      ao, MTOT, 1024, 1024, 1024, 1024, 1024);

    // h1 = LN(h + ao)
    ln_kernel<<<MTOT, 256>>>(h, ao, n1g, n1b, h1);

    // FFN
    sgemm_kernel<2><<<dim3(32, MTOT / GBM), 256>>>(h1,  fw1, fb1, ffi, MTOT, 4096, 1024, 1024, 4096, 4096);
    sgemm_kernel<1><<<dim3(8,  MTOT / GBM), 256>>>(ffi, fw2, fb2, ff2, MTOT, 1024, 4096, 4096, 1024, 1024);

    // out = LN(h1 + ff2)
    ln_kernel<<<MTOT, 256>>>(h1, ff2, n2g, n2b, out);
}

// round 4
// speedup vs baseline: 3.2736x; 3.2736x over previous
#include <cuda_runtime.h>
#include <math.h>

// Problem constants
#define BB   4
#define NTOK 4096
#define DM   1024
#define DH   256
#define SM_  256
#define HIDN 32
#define MTOT (BB*NTOK)   // 16384

// ---------------- scratch ----------------
__device__ float g_ctx[BB*DM];
__device__ float g_gamma[BB];
__device__ float g_p[MTOT];
__device__ float g_ppc[(size_t)MTOT*512];     // [pr | pi]
__device__ float g_Bcat[512*512];             // [[Mr^T, Mi^T],[Mi^T, -Mr^T]]
__device__ float g_reim[(size_t)MTOT*512];    // [re | im]
__device__ float g_attn[(size_t)MTOT*256];
__device__ float g_av[(size_t)MTOT*1024];
__device__ float g_ao[(size_t)MTOT*1024];
__device__ float g_h1[(size_t)MTOT*1024];
__device__ float g_ffi[(size_t)MTOT*4096];
__device__ float g_ff2[(size_t)MTOT*1024];

__device__ __forceinline__ float warp_sum(float v) {
#pragma unroll
    for (int o = 16; o > 0; o >>= 1) v += __shfl_xor_sync(0xffffffffu, v, o);
    return v;
}
__device__ __forceinline__ float gelu_exact(float x) {
    return 0.5f * x * (1.0f + erff(x * 0.70710678118654752440f));
}

// ---------------- ctx = mean over N ----------------
__global__ void ctx_kernel(const float* __restrict__ h) {
    int d = blockIdx.x * blockDim.x + threadIdx.x;
    int b = blockIdx.y;
    const float* hp = h + ((size_t)b * NTOK) * DM + d;
    float s = 0.f;
    for (int n = 0; n < NTOK; n++) s += hp[(size_t)n * DM];
    g_ctx[b * DM + d] = s * (1.0f / NTOK);
}

// ---------------- gamma gate ----------------
__global__ void gamma_kernel(const float* __restrict__ gw1, const float* __restrict__ gb1,
                             const float* __restrict__ gg,  const float* __restrict__ gbeta,
                             const float* __restrict__ gw2, const float* __restrict__ gb2) {
    int b = blockIdx.x;
    int j = threadIdx.x;
    const float* c = g_ctx + b * DM;
    float t = gb1[j];
    for (int k = 0; k < DM; k++) t += c[k] * gw1[k * HIDN + j];
    float mu  = warp_sum(t) * (1.f / 32.f);
    float dv  = t - mu;
    float var = warp_sum(dv * dv) * (1.f / 32.f);
    float tn  = dv * rsqrtf(var + 1e-5f) * gg[j] + gbeta[j];
    float s   = tn / (1.f + expf(-tn));
    float z   = warp_sum(s * gw2[j]);
    if (j == 0) g_gamma[b] = 1.f / (1.f + expf(-(z + gb2[0])));
}

// ---------------- normalize memory + build Bcat ----------------
__global__ void mem_kernel(const float* __restrict__ m_real, const float* __restrict__ m_imag) {
    int s = blockIdx.x;
    int k = threadIdx.x;
    float mr = m_real[s * DH + k];
    float mi = m_imag[s * DH + k];
    __shared__ float red[256];
    red[k] = mr * mr + mi * mi;
    __syncthreads();
    for (int o = 128; o > 0; o >>= 1) { if (k < o) red[k] += red[k + o]; __syncthreads(); }
    __shared__ float sc;
    if (k == 0) sc = 1.f / fmaxf(sqrtf(red[0]), 1e-12f);
    __syncthreads();
    float a = mr * sc, b = mi * sc;
    g_Bcat[k * 512 + s]               = a;
    g_Bcat[(256 + k) * 512 + s]       = b;
    g_Bcat[k * 512 + 256 + s]         = b;
    g_Bcat[(256 + k) * 512 + 256 + s] = -a;
}

// ---------------- per-token: normalize psi, uncertainty gate, p ----------------
__global__ void rownorm_gate_kernel(const float* __restrict__ h,
    const float* __restrict__ uw1, const float* __restrict__ ub1,
    const float* __restrict__ ug,  const float* __restrict__ ubeta,
    const float* __restrict__ uw2, const float* __restrict__ ub2) {
    int m = blockIdx.x;
    int tid = threadIdx.x;
    float* row = g_ppc + (size_t)m * 512;
    float v0 = row[tid], v1 = row[256 + tid];
    __shared__ float red[256];
    red[tid] = v0 * v0 + v1 * v1;
    __syncthreads();
    for (int o = 128; o > 0; o >>= 1) { if (tid < o) red[tid] += red[tid + o]; __syncthreads(); }
    __shared__ float sc;
    if (tid == 0) sc = 1.f / fmaxf(sqrtf(red[0]), 1e-12f);
    __syncthreads();
    row[tid] = v0 * sc;
    row[256 + tid] = v1 * sc;

    int j = tid & 31, part = tid >> 5;
    const float* hr = h + (size_t)m * DM;
    float partial = 0.f;
    int k0 = part * 128;
    for (int k = k0; k < k0 + 128; k++) partial += hr[k] * uw1[k * HIDN + j];
    __shared__ float gred[8][32];
    gred[part][j] = partial;
    __syncthreads();
    if (tid < 32) {
        float t = ub1[tid];
#pragma unroll
        for (int q = 0; q < 8; q++) t += gred[q][tid];
        float mu  = warp_sum(t) * (1.f / 32.f);
        float dv  = t - mu;
        float var = warp_sum(dv * dv) * (1.f / 32.f);
        float tn  = dv * rsqrtf(var + 1e-5f) * ug[tid] + ubeta[tid];
        float s   = tn / (1.f + expf(-tn));
        float z   = warp_sum(s * uw2[tid]);
        if (tid == 0) {
            float pin = 0.95f / (1.f + expf(-(z + ub2[0])));
            g_p[m] = pin * (1.f - g_gamma[m >> 12]);
        }
    }
}

// ---------------- attention row normalize ----------------
__global__ void attn_kernel() {
    int m = blockIdx.x;
    int s = threadIdx.x;
    float re = g_reim[(size_t)m * 512 + s];
    float im = g_reim[(size_t)m * 512 + 256 + s];
    float pm = g_p[m];
    float raw = (1.f - pm) * (re * re + im * im) + pm * (1.f / 256.f);
    __shared__ float red[256];
    red[s] = raw;
    __syncthreads();
    for (int o = 128; o > 0; o >>= 1) { if (s < o) red[s] += red[s + o]; __syncthreads(); }
    g_attn[(size_t)m * 256 + s] = raw / (red[0] + 1e-8f);
}

// ---------------- LayerNorm(x + y) ----------------
__global__ void ln_kernel(const float* __restrict__ x, const float* __restrict__ y,
                          const float* __restrict__ g, const float* __restrict__ bta,
                          float* __restrict__ out) {
    int m = blockIdx.x;
    int tid = threadIdx.x;
    size_t base = (size_t)m * DM;
    float v[4];
    float s1 = 0.f, s2 = 0.f;
#pragma unroll
    for (int i = 0; i < 4; i++) {
        int d = tid + 256 * i;
        v[i] = x[base + d] + y[base + d];
        s1 += v[i];
        s2 += v[i] * v[i];
    }
    __shared__ float r1[256], r2[256];
    r1[tid] = s1; r2[tid] = s2;
    __syncthreads();
    for (int o = 128; o > 0; o >>= 1) {
        if (tid < o) { r1[tid] += r1[tid + o]; r2[tid] += r2[tid + o]; }
        __syncthreads();
    }
    float mu  = r1[0] * (1.f / 1024.f);
    float var = r2[0] * (1.f / 1024.f) - mu * mu;
    float inv = rsqrtf(var + 1e-5f);
#pragma unroll
    for (int i = 0; i < 4; i++) {
        int d = tid + 256 * i;
        out[base + d] = (v[i] - mu) * inv * g[d] + bta[d];
    }
}

// ================= tf32 tensor-core GEMM =================
// C(MxN) = A(MxK, row-major) @ B(KxN, row-major) [+bias][+gelu]
// CTA tile 128x128x16, 4 warps, warp tile 64x64 (4 m-subtiles x 8 n-subtiles),
// mma.m16n8k8.tf32 (fp32 bits fed directly; HW truncates to tf32).
#define TBM 128
#define TBN 128
#define TBK 16
#define AST 20     // As row stride (16 + 4 pad) -> conflict-free fragment LDS
#define BST 132    // Bs row stride (128 + 4 pad)

__device__ __forceinline__ void cp_async16(void* sdst, const void* gsrc) {
    unsigned s = (unsigned)__cvta_generic_to_shared(sdst);
    asm volatile("cp.async.cg.shared.global [%0], [%1], 16;\n" :: "r"(s), "l"(gsrc));
}
__device__ __forceinline__ void cp_commit() { asm volatile("cp.async.commit_group;\n"); }
__device__ __forceinline__ void cp_wait1()  { asm volatile("cp.async.wait_group 1;\n"); }
__device__ __forceinline__ void cp_wait0()  { asm volatile("cp.async.wait_group 0;\n"); }

__device__ __forceinline__ void mma_tf32(float* d, const unsigned* a, const unsigned* b) {
    asm volatile(
        "mma.sync.aligned.m16n8k8.row.col.f32.tf32.tf32.f32 "
        "{%0,%1,%2,%3}, {%4,%5,%6,%7}, {%8,%9}, {%0,%1,%2,%3};"
        : "+f"(d[0]), "+f"(d[1]), "+f"(d[2]), "+f"(d[3])
        : "r"(a[0]), "r"(a[1]), "r"(a[2]), "r"(a[3]), "r"(b[0]), "r"(b[1]));
}

template <int EPI>  // 0: none, 1: +bias, 2: +bias+gelu
__global__ __launch_bounds__(128) void tgemm_kernel(
    const float* __restrict__ A, const float* __restrict__ B,
    const float* __restrict__ bias, float* __restrict__ C,
    int M, int N, int K, int lda, int ldb, int ldc) {
    __shared__ float As[2][TBM * AST];
    __shared__ float Bs[2][TBK * BST];

    int tid  = threadIdx.x;
    int warp = tid >> 5, lane = tid & 31;
    int g = lane >> 2, tg = lane & 3;
    int wm = warp >> 1, wn = warp & 1;
    int row0 = blockIdx.y * TBM, col0 = blockIdx.x * TBN;

    // load mapping: 512 float4 chunks per matrix, 4 per thread
    int am[4], ak[4], bk[4], bn[4];
#pragma unroll
    for (int i = 0; i < 4; i++) {
        int c = tid + i * 128;
        am[i] = c >> 2;  ak[i] = (c & 3) * 4;
        bk[i] = c >> 5;  bn[i] = (c & 31) * 4;
    }

    float acc[4][8][4];
#pragma unroll
    for (int mi = 0; mi < 4; mi++)
#pragma unroll
        for (int ni = 0; ni < 8; ni++)
#pragma unroll
            for (int r = 0; r < 4; r++) acc[mi][ni][r] = 0.f;

    int T = K / TBK;

    // prologue: stage 0
    {
#pragma unroll
        for (int i = 0; i < 4; i++)
            cp_async16(&As[0][am[i] * AST + ak[i]],
                       A + (size_t)(row0 + am[i]) * lda + ak[i]);
#pragma unroll
        for (int i = 0; i < 4; i++)
            cp_async16(&Bs[0][bk[i] * BST + bn[i]],
                       B + (size_t)bk[i] * ldb + col0 + bn[i]);
        cp_commit();
    }

    for (int t = 0; t < T; t++) {
        if (t + 1 < T) {
            int s = (t + 1) & 1, k0 = (t + 1) * TBK;
#pragma unroll
            for (int i = 0; i < 4; i++)
                cp_async16(&As[s][am[i] * AST + ak[i]],
                           A + (size_t)(row0 + am[i]) * lda + k0 + ak[i]);
#pragma unroll
            for (int i = 0; i < 4; i++)
                cp_async16(&Bs[s][bk[i] * BST + bn[i]],
                           B + (size_t)(k0 + bk[i]) * ldb + col0 + bn[i]);
            cp_commit();
            cp_wait1();
        } else {
            cp_wait0();
        }
        __syncthreads();

        const unsigned* as = (const unsigned*)As[t & 1];
        const unsigned* bs = (const unsigned*)Bs[t & 1];
#pragma unroll
        for (int kk = 0; kk < TBK; kk += 8) {
            unsigned af[4][4], bf[8][2];
#pragma unroll
            for (int mi = 0; mi < 4; mi++) {
                int r = wm * 64 + mi * 16 + g;
                int c = kk + tg;
                af[mi][0] = as[r * AST + c];
                af[mi][1] = as[(r + 8) * AST + c];
                af[mi][2] = as[r * AST + c + 4];
                af[mi][3] = as[(r + 8) * AST + c + 4];
            }
#pragma unroll
            for (int ni = 0; ni < 8; ni++) {
                int c = wn * 64 + ni * 8 + g;
                bf[ni][0] = bs[(kk + tg) * BST + c];
                bf[ni][1] = bs[(kk + tg + 4) * BST + c];
            }
#pragma unroll
            for (int mi = 0; mi < 4; mi++)
#pragma unroll
                for (int ni = 0; ni < 8; ni++)
                    mma_tf32(acc[mi][ni], af[mi], bf[ni]);
        }
        __syncthreads();
    }

    // epilogue
#pragma unroll
    for (int mi = 0; mi < 4; mi++) {
        int r0 = row0 + wm * 64 + mi * 16 + g;
        int r1 = r0 + 8;
#pragma unroll
        for (int ni = 0; ni < 8; ni++) {
            int c = col0 + wn * 64 + ni * 8 + 2 * tg;
            float b0 = 0.f, b1 = 0.f;
            if (EPI > 0) { b0 = bias[c]; b1 = bias[c + 1]; }
            float v0 = acc[mi][ni][0] + b0;
            float v1 = acc[mi][ni][1] + b1;
            float v2 = acc[mi][ni][2] + b0;
            float v3 = acc[mi][ni][3] + b1;
            if (EPI == 2) {
                v0 = gelu_exact(v0); v1 = gelu_exact(v1);
                v2 = gelu_exact(v2); v3 = gelu_exact(v3);
            }
            *(float2*)(C + (size_t)r0 * ldc + c) = make_float2(v0, v1);
            *(float2*)(C + (size_t)r1 * ldc + c) = make_float2(v2, v3);
        }
    }
}

// ---------------- launch ----------------
extern "C" void kernel_launch(void* const* d_in, const int* in_sizes, int n_in,
                              void* d_out, int out_size) {
    const float* h      = (const float*)d_in[0];
    const float* Wr     = (const float*)d_in[1];
    const float* br     = (const float*)d_in[2];
    const float* Wi     = (const float*)d_in[3];
    const float* bi     = (const float*)d_in[4];
    const float* uw1    = (const float*)d_in[5];
    const float* ub1    = (const float*)d_in[6];
    const float* ug     = (const float*)d_in[7];
    const float* ubeta  = (const float*)d_in[8];
    const float* uw2    = (const float*)d_in[9];
    const float* ub2    = (const float*)d_in[10];
    const float* gw1    = (const float*)d_in[11];
    const float* gb1    = (const float*)d_in[12];
    const float* gg     = (const float*)d_in[13];
    const float* gbeta  = (const float*)d_in[14];
    const float* gw2    = (const float*)d_in[15];
    const float* gb2    = (const float*)d_in[16];
    const float* m_real = (const float*)d_in[17];
    const float* m_imag = (const float*)d_in[18];
    const float* values = (const float*)d_in[19];
    const float* ow     = (const float*)d_in[20];
    const float* ob     = (const float*)d_in[21];
    const float* n1g    = (const float*)d_in[22];
    const float* n1b    = (const float*)d_in[23];
    const float* n2g    = (const float*)d_in[24];
    const float* n2b    = (const float*)d_in[25];
    const float* fw1    = (const float*)d_in[26];
    const float* fb1    = (const float*)d_in[27];
    const float* fw2    = (const float*)d_in[28];
    const float* fb2    = (const float*)d_in[29];
    float* out = (float*)d_out;

    float *ppc, *Bcat, *reim, *attn, *av, *ao, *h1, *ffi, *ff2;
    cudaGetSymbolAddress((void**)&ppc,  g_ppc);
    cudaGetSymbolAddress((void**)&Bcat, g_Bcat);
    cudaGetSymbolAddress((void**)&reim, g_reim);
    cudaGetSymbolAddress((void**)&attn, g_attn);
    cudaGetSymbolAddress((void**)&av,   g_av);
    cudaGetSymbolAddress((void**)&ao,   g_ao);
    cudaGetSymbolAddress((void**)&h1,   g_h1);
    cudaGetSymbolAddress((void**)&ffi,  g_ffi);
    cudaGetSymbolAddress((void**)&ff2,  g_ff2);

    ctx_kernel<<<dim3(DM / 256, BB), 256>>>(h);
    gamma_kernel<<<BB, 32>>>(gw1, gb1, gg, gbeta, gw2, gb2);
    mem_kernel<<<SM_, 256>>>(m_real, m_imag);

    // encoder: pr | pi -> ppc (M,512)
    tgemm_kernel<1><<<dim3(2, MTOT / TBM), 128>>>(h, Wr, br, ppc,       MTOT, 256,  1024, 1024, 256,  512);
    tgemm_kernel<1><<<dim3(2, MTOT / TBM), 128>>>(h, Wi, bi, ppc + 256, MTOT, 256,  1024, 1024, 256,  512);

    rownorm_gate_kernel<<<MTOT, 256>>>(h, uw1, ub1, ug, ubeta, uw2, ub2);

    // complex overlap: reim = ppc @ Bcat (M,512)
    tgemm_kernel<0><<<dim3(4, MTOT / TBM), 128>>>(ppc, Bcat, nullptr, reim, MTOT, 512,  512,  512,  512,  512);

    attn_kernel<<<MTOT, 256>>>();

    tgemm_kernel<0><<<dim3(8, MTOT / TBM), 128>>>(attn, values, nullptr, av, MTOT, 1024, 256,  256,  1024, 1024);
    tgemm_kernel<1><<<dim3(8, MTOT / TBM), 128>>>(av,   ow,     ob,      ao, MTOT, 1024, 1024, 1024, 1024, 1024);

    ln_kernel<<<MTOT, 256>>>(h, ao, n1g, n1b, h1);

    tgemm_kernel<2><<<dim3(32, MTOT / TBM), 128>>>(h1,  fw1, fb1, ffi, MTOT, 4096, 1024, 1024, 4096, 4096);
    tgemm_kernel<1><<<dim3(8,  MTOT / TBM), 128>>>(ffi, fw2, fb2, ff2, MTOT, 1024, 4096, 4096, 1024, 1024);

    ln_kernel<<<MTOT, 256>>>(h1, ff2, n2g, n2b, out);
}